// round 1
// baseline (speedup 1.0000x reference)
#include <cuda_runtime.h>
#include <math.h>

#define Nn 2048
#define Dd 256
#define Qq 16
#define Mm 64
#define MMs (Mm*Mm)
#define NPAIR 2080

// -------- scratch (device globals; no allocation) --------
__device__ alignas(16) float g_row[Nn*32];     // per-n: u[16], w2[16]
__device__ float  g_a[Nn];                     // per-n exponent constant
__device__ float  g_w1[Nn*Qq];
__device__ float  g_c1[Nn];
__device__ float  g_kmm[MMs];
__device__ float  g_ub[NPAIR];
__device__ int    g_upI[NPAIR];
__device__ int    g_upJ[NPAIR];
__device__ alignas(16) float4 g_uz4[NPAIR*8];  // per-pair: zbar[16], -zbar^2[16]
__device__ float  g_psi2[MMs];
__device__ alignas(16) float g_psi1[Nn*Mm];
__device__ float  g_A[Mm*Dd];
__device__ float  g_invC[MMs];
__device__ float  g_scal[8];  // 0 kl, 1 yy, 2 AB, 3 ld_kmm, 4 ld_cov1, 5 trace

__device__ __forceinline__ float softplus_f(float x) {
    float ax = fabsf(x);
    return fmaxf(x, 0.0f) + log1pf(__expf(-ax));
}

__device__ __forceinline__ float blockReduce256(float v, float* red) {
    int t = threadIdx.x;
    red[t] = v; __syncthreads();
    #pragma unroll
    for (int s = 128; s > 0; s >>= 1) {
        if (t < s) red[t] += red[t + s];
        __syncthreads();
    }
    return red[0];
}

// -------- K0: zero accumulators --------
__global__ void k0_zero() {
    int i = blockIdx.x * 256 + threadIdx.x;
    if (i < MMs)      g_psi2[i] = 0.0f;
    if (i < Mm*Dd)    g_A[i]    = 0.0f;
    if (i < 8)        g_scal[i] = 0.0f;
}

// -------- K1: per-n statistics + KL --------
__global__ void k1_pern(const float* __restrict__ qmu,
                        const float* __restrict__ qls,
                        const float* __restrict__ alpha,
                        const float* __restrict__ varp) {
    __shared__ float red[256];
    int n = blockIdx.x * 256 + threadIdx.x;
    float lv = logf(varp[0]);
    float sum2 = 0.f, s3 = 0.f, P = 0.f, kl = 0.f;
    #pragma unroll
    for (int q = 0; q < Qq; q++) {
        float mu = qmu[n*Qq + q];
        float sg = softplus_f(qls[n*Qq + q]);
        float al = alpha[q];
        kl += -logf(sg) + 0.5f*(sg*sg + mu*mu - 1.0f);
        float d1 = sg*al + 1.0f;
        g_w1[n*Qq + q] = al / d1;
        sum2 += logf(d1);
        float d2 = 2.0f*al*sg + 1.0f;
        float w2 = al / d2;
        s3 += logf(d2);
        P += w2*mu*mu;
        g_row[n*32 + q]      = 2.0f*w2*mu;
        g_row[n*32 + 16 + q] = w2;
    }
    g_c1[n] = 2.0f*lv - 0.5f*sum2;
    g_a[n]  = 4.0f*lv - 0.5f*s3 - P;
    float tot = blockReduce256(kl, red);
    if (threadIdx.x == 0) atomicAdd(&g_scal[0], tot);
}

// -------- K2: pairwise z statistics: k_mm, upper-tri pair tables --------
__global__ void k2_pairs(const float* __restrict__ z,
                         const float* __restrict__ alpha,
                         const float* __restrict__ varp) {
    __shared__ float zs[Mm*Qq];
    __shared__ float sal[Qq];
    int tid = threadIdx.x;
    for (int t = tid; t < Mm*Qq; t += 256) zs[t] = z[t];
    if (tid < Qq) sal[tid] = alpha[tid];
    __syncthreads();
    float var = varp[0];
    for (int p = tid; p < MMs; p += 256) {
        int i = p >> 6, j = p & 63;
        float S = 0.f;
        #pragma unroll
        for (int q = 0; q < Qq; q++) {
            float dz = zs[i*Qq + q] - zs[j*Qq + q];
            S += sal[q]*dz*dz;
        }
        g_kmm[p] = var * __expf(-0.5f*S);
        if (i <= j) {
            int u = i*Mm - (i*(i-1))/2 + (j - i);
            g_upI[u] = i; g_upJ[u] = j;
            g_ub[u]  = -0.25f*S;
            float zb[Qq];
            #pragma unroll
            for (int q = 0; q < Qq; q++) zb[q] = 0.5f*(zs[i*Qq+q] + zs[j*Qq+q]);
            #pragma unroll
            for (int k4 = 0; k4 < 4; k4++)
                g_uz4[u*8 + k4] = make_float4(zb[4*k4], zb[4*k4+1], zb[4*k4+2], zb[4*k4+3]);
            #pragma unroll
            for (int k4 = 0; k4 < 4; k4++)
                g_uz4[u*8 + 4 + k4] = make_float4(-zb[4*k4]*zb[4*k4],   -zb[4*k4+1]*zb[4*k4+1],
                                                  -zb[4*k4+2]*zb[4*k4+2], -zb[4*k4+3]*zb[4*k4+3]);
        }
    }
}

// -------- K3: psi2 accumulation (symmetric half) --------
// grid (9, 16): pair groups of 256, n-chunks of 128
__global__ void k3_psi2() {
    __shared__ alignas(16) float sR[8][36];  // u[16],w[16], a at [32]
    int tid = threadIdx.x;
    int p = blockIdx.x * 256 + tid;
    bool valid = p < NPAIR;
    int pp = valid ? p : 0;
    float4 zc[8];
    #pragma unroll
    for (int k = 0; k < 8; k++) zc[k] = g_uz4[pp*8 + k];
    float b = g_ub[pp];
    int n0 = blockIdx.y * 128;
    float acc = 0.f;
    for (int c = 0; c < 128; c += 8) {
        __syncthreads();
        for (int t = tid; t < 8*33; t += 256) {
            int i = t / 33, k = t - i*33;
            sR[i][k] = (k < 32) ? g_row[(n0 + c + i)*32 + k] : g_a[n0 + c + i];
        }
        __syncthreads();
        #pragma unroll
        for (int i = 0; i < 8; i++) {
            const float4* rv = (const float4*)&sR[i][0];
            float dot = b + sR[i][32];
            #pragma unroll
            for (int k = 0; k < 8; k++) {
                float4 r = rv[k];
                dot = fmaf(r.x, zc[k].x, dot);
                dot = fmaf(r.y, zc[k].y, dot);
                dot = fmaf(r.z, zc[k].z, dot);
                dot = fmaf(r.w, zc[k].w, dot);
            }
            acc += __expf(dot);
        }
    }
    if (valid) {
        int i = g_upI[p], j = g_upJ[p];
        atomicAdd(&g_psi2[i*Mm + j], acc);
        if (i != j) atomicAdd(&g_psi2[j*Mm + i], acc);
    }
}

// -------- K4: psi1 (n x m) --------
__global__ void k4_psi1(const float* __restrict__ qmu,
                        const float* __restrict__ z) {
    __shared__ float zs[Mm*Qq];
    int tid = threadIdx.x;
    for (int t = tid; t < Mm*Qq; t += 256) zs[t] = z[t];
    __syncthreads();
    int idx = blockIdx.x * 256 + tid;
    int n = idx >> 6, j = idx & 63;
    float s = 0.f;
    #pragma unroll
    for (int q = 0; q < Qq; q++) {
        float dm = qmu[n*Qq + q] - zs[j*Qq + q];
        s = fmaf(g_w1[n*Qq + q], dm*dm, s);
    }
    g_psi1[n*Mm + j] = __expf(g_c1[n] - 0.5f*s);
}

// -------- K5: A = psi1^T @ y  and sum(y*y) --------
// grid (8 dchunks, 16 nchunks), 256 threads = 8 jgroups x 32 dcols
__global__ void k5_A(const float* __restrict__ y) {
    __shared__ alignas(16) float sP[16][64];
    __shared__ float red[256];
    int tid = threadIdx.x;
    int jg = tid >> 5, dc = tid & 31;
    int d0 = blockIdx.x * 32;
    int n0 = blockIdx.y * 128;
    float acc[8] = {0,0,0,0,0,0,0,0};
    float yy = 0.f;
    for (int s = 0; s < 128; s += 16) {
        __syncthreads();
        {
            int row = tid >> 4, c4 = tid & 15;
            ((float4*)&sP[row][0])[c4] = ((const float4*)&g_psi1[(n0 + s + row)*Mm])[c4];
        }
        __syncthreads();
        #pragma unroll
        for (int nn = 0; nn < 16; nn++) {
            float yv = y[(n0 + s + nn)*Dd + d0 + dc];
            if (jg == 0) yy = fmaf(yv, yv, yy);
            float4 p0 = ((const float4*)&sP[nn][0])[jg*2];
            float4 p1 = ((const float4*)&sP[nn][0])[jg*2 + 1];
            acc[0] = fmaf(p0.x, yv, acc[0]); acc[1] = fmaf(p0.y, yv, acc[1]);
            acc[2] = fmaf(p0.z, yv, acc[2]); acc[3] = fmaf(p0.w, yv, acc[3]);
            acc[4] = fmaf(p1.x, yv, acc[4]); acc[5] = fmaf(p1.y, yv, acc[5]);
            acc[6] = fmaf(p1.z, yv, acc[6]); acc[7] = fmaf(p1.w, yv, acc[7]);
        }
    }
    #pragma unroll
    for (int jj = 0; jj < 8; jj++)
        atomicAdd(&g_A[(jg*8 + jj)*Dd + d0 + dc], acc[jj]);
    float tot = blockReduce256(yy, red);
    if (tid == 0) atomicAdd(&g_scal[1], tot);
}

// -------- K6: two concurrent Gauss-Jordan inversions (block0: kmm, block1: cov1) --------
__global__ void k6_gj(const float* __restrict__ noise) {
    __shared__ alignas(16) float sG[Mm][132];
    __shared__ alignas(16) float pr[128];
    __shared__ float red[256];
    int tid = threadIdx.x;
    int b = blockIdx.x;
    float beta = 1.0f / softplus_f(noise[0]);
    for (int p = tid; p < MMs; p += 256) {
        int i = p >> 6, j = p & 63;
        float v = g_kmm[p];
        if (b == 1) v = fmaf(beta, g_psi2[p], v);
        sG[i][j] = v;
        sG[i][64 + j] = (i == j) ? 1.0f : 0.0f;
    }
    __syncthreads();
    int r = tid >> 2, c0 = tid & 3;
    float ld = 0.f;
    for (int k = 0; k < Mm; k++) {
        float piv = sG[k][k];
        float rp = 1.0f / piv;
        ld += logf(piv);
        float f = sG[r][k];
        if (tid < 128) pr[tid] = sG[k][tid] * rp;
        __syncthreads();
        if (r == k) {
            #pragma unroll
            for (int t4 = 0; t4 < 8; t4++) {
                int j4 = c0 + 4*t4;
                ((float4*)&sG[r][0])[j4] = ((float4*)pr)[j4];
            }
        } else {
            #pragma unroll
            for (int t4 = 0; t4 < 8; t4++) {
                int j4 = c0 + 4*t4;
                float4 pv = ((float4*)pr)[j4];
                float4 g  = ((float4*)&sG[r][0])[j4];
                g.x = fmaf(-f, pv.x, g.x);
                g.y = fmaf(-f, pv.y, g.y);
                g.z = fmaf(-f, pv.z, g.z);
                g.w = fmaf(-f, pv.w, g.w);
                ((float4*)&sG[r][0])[j4] = g;
            }
        }
        __syncthreads();
    }
    if (b == 0) {
        // trace(kmm^{-1} psi2) = sum_ij invK[i][j]*psi2[i][j] (both symmetric)
        float tp = 0.f;
        for (int p = tid; p < MMs; p += 256) {
            int i = p >> 6, j = p & 63;
            tp = fmaf(sG[i][64 + j], g_psi2[p], tp);
        }
        float tot = blockReduce256(tp, red);
        if (tid == 0) { g_scal[3] = ld; g_scal[5] = tot; }
    } else {
        for (int p = tid; p < MMs; p += 256) {
            int i = p >> 6, j = p & 63;
            g_invC[p] = sG[i][64 + j];
        }
        if (tid == 0) g_scal[4] = ld;
    }
}

// -------- K6b: sum(A * (cov1^{-1} A)) via explicit inverse --------
__global__ void k6b_AB() {
    __shared__ float red[256];
    int j = blockIdx.x;
    int c = threadIdx.x;
    float bv = 0.f;
    #pragma unroll 8
    for (int k = 0; k < Mm; k++)
        bv = fmaf(g_invC[j*Mm + k], g_A[k*Dd + c], bv);
    float part = g_A[j*Dd + c] * bv;
    float tot = blockReduce256(part, red);
    if (c == 0) atomicAdd(&g_scal[2], tot);
}

// -------- K7: final assembly --------
__global__ void k7_final(const float* __restrict__ noise,
                         const float* __restrict__ varp,
                         float* __restrict__ out) {
    if (threadIdx.x != 0) return;
    float var = varp[0];
    float beta = 1.0f / softplus_f(noise[0]);
    double nd = (double)Nn * (double)Dd;
    double kl = (double)g_scal[0] / nd;
    double F = 0.5 * Nn * log((double)beta)
             + 0.5 * (double)g_scal[3]
             - 0.5 * Nn * log(3.14159265358979323846)
             - 0.5 * (double)g_scal[4]
             - 0.5 * (double)beta * ((double)Nn * var)
             + 0.5 * (double)g_scal[5];
    double tr_yWy = (double)beta * (double)g_scal[1] - (double)g_scal[2];
    F = (F * Dd - 0.5 * tr_yWy) / nd;
    out[0] = (float)(F - kl);
}

extern "C" void kernel_launch(void* const* d_in, const int* in_sizes, int n_in,
                              void* d_out, int out_size) {
    const float* y     = (const float*)d_in[0];
    const float* qmu   = (const float*)d_in[1];
    const float* qls   = (const float*)d_in[2];
    const float* z     = (const float*)d_in[3];
    const float* noise = (const float*)d_in[4];
    const float* alpha = (const float*)d_in[5];
    const float* varp  = (const float*)d_in[6];
    float* out = (float*)d_out;

    k0_zero<<<81, 256>>>();
    k1_pern<<<Nn/256, 256>>>(qmu, qls, alpha, varp);
    k2_pairs<<<1, 256>>>(z, alpha, varp);
    k3_psi2<<<dim3(9, 16), 256>>>();
    k4_psi1<<<(Nn*Mm)/256, 256>>>(qmu, z);
    k5_A<<<dim3(8, 16), 256>>>(y);
    k6_gj<<<2, 256>>>(noise);
    k6b_AB<<<Mm, 256>>>();
    k7_final<<<1, 32>>>(noise, varp, out);
}

// round 2
// speedup vs baseline: 1.1262x; 1.1262x over previous
#include <cuda_runtime.h>
#include <math.h>

#define Nn 2048
#define Dd 256
#define Qq 16
#define Mm 64
#define MMs 4096
#define NPAIR 2080
#define NPAD 2560
#define LOG2E 1.4426950408889634f

// -------- scratch (device globals; zero-initialized at load) --------
__device__ alignas(16) float g_row[Nn*32];    // psi2 per-n row: u'[16], w'[16] (log2e-scaled)
__device__ float  g_a[Nn];                    // psi2 per-n const (log2e-scaled)
__device__ alignas(16) float g_pp[Nn*36];     // psi1 per-n: qmu[16], w1''[16], c1'[1]
__device__ alignas(16) float g_kmm[MMs];
__device__ float  g_ub[NPAD];                 // per-pair const (log2e-scaled)
__device__ int    g_upI[NPAD];
__device__ int    g_upJ[NPAD];
__device__ alignas(16) float4 g_uz4[NPAD*8];  // per-pair: zbar[16], -zbar^2[16]
__device__ alignas(16) float g_psi2[MMs];
__device__ alignas(16) float g_A[Mm*Dd];
__device__ alignas(16) float g_G[MMs];        // A @ A^T
__device__ float  g_klpart[8];
__device__ float  g_scal[8];                  // [1] = sum(y*y)

__device__ __forceinline__ float softplus_f(float x) {
    float ax = fabsf(x);
    return fmaxf(x, 0.0f) + log1pf(__expf(-ax));
}
__device__ __forceinline__ float ex2(float x) {
    float y; asm("ex2.approx.f32 %0, %1;" : "=f"(y) : "f"(x)); return y;
}

// ================= kA: zero + per-n stats + pair tables (17 blocks) =========
__global__ void kA(const float* __restrict__ qmu, const float* __restrict__ qls,
                   const float* __restrict__ z,   const float* __restrict__ alpha,
                   const float* __restrict__ varp) {
    int bx = blockIdx.x, tid = threadIdx.x;
    if (bx < 8) {
        // ---- per-n statistics + KL partial ----
        __shared__ float red[256];
        int n = bx * 256 + tid;
        float lv = logf(varp[0]);
        float sum2 = 0.f, s3 = 0.f, P = 0.f, kl = 0.f;
        #pragma unroll
        for (int q = 0; q < Qq; q++) {
            float mu = qmu[n*Qq + q];
            float sg = softplus_f(qls[n*Qq + q]);
            float al = alpha[q];
            kl += -logf(sg) + 0.5f*(sg*sg + mu*mu - 1.0f);
            float d1 = sg*al + 1.0f;
            float d2 = 2.0f*al*sg + 1.0f;
            float w1 = al / d1;
            float w2 = al / d2;
            sum2 += logf(d1);
            s3   += logf(d2);
            P    += w2*mu*mu;
            g_row[n*32 + q]      = LOG2E * 2.0f * w2 * mu;
            g_row[n*32 + 16 + q] = LOG2E * w2;
            g_pp[n*36 + q]       = mu;
            g_pp[n*36 + 16 + q]  = 0.5f * LOG2E * w1;   // fold the 0.5
        }
        g_pp[n*36 + 32] = LOG2E * (2.0f*lv - 0.5f*sum2);   // c1'
        g_a[n]          = LOG2E * (4.0f*lv - 0.5f*s3 - P); // a'
        red[tid] = kl; __syncthreads();
        #pragma unroll
        for (int s = 128; s > 0; s >>= 1) { if (tid < s) red[tid] += red[tid+s]; __syncthreads(); }
        if (tid == 0) g_klpart[bx] = red[0];
    } else if (bx == 8) {
        // ---- pairwise z statistics: k_mm + pair tables ----
        __shared__ float zsh[Mm*Qq];
        __shared__ float sal[Qq];
        for (int t = tid; t < Mm*Qq; t += 256) zsh[t] = z[t];
        if (tid < Qq) sal[tid] = alpha[tid];
        __syncthreads();
        float var = varp[0];
        for (int p = tid; p < MMs; p += 256) {
            int i = p >> 6, j = p & 63;
            float S = 0.f;
            #pragma unroll
            for (int q = 0; q < Qq; q++) {
                float dz = zsh[i*Qq + q] - zsh[j*Qq + q];
                S = fmaf(sal[q]*dz, dz, S);
            }
            g_kmm[p] = var * __expf(-0.5f*S);
            if (i <= j) {
                int u = i*Mm - (i*(i-1))/2 + (j - i);
                g_upI[u] = i; g_upJ[u] = j;
                g_ub[u]  = -0.25f * LOG2E * S;
                float zb[Qq];
                #pragma unroll
                for (int q = 0; q < Qq; q++) zb[q] = 0.5f*(zsh[i*Qq+q] + zsh[j*Qq+q]);
                #pragma unroll
                for (int k4 = 0; k4 < 4; k4++)
                    g_uz4[u*8 + k4] = make_float4(zb[4*k4], zb[4*k4+1], zb[4*k4+2], zb[4*k4+3]);
                #pragma unroll
                for (int k4 = 0; k4 < 4; k4++)
                    g_uz4[u*8 + 4 + k4] = make_float4(-zb[4*k4]*zb[4*k4],     -zb[4*k4+1]*zb[4*k4+1],
                                                      -zb[4*k4+2]*zb[4*k4+2], -zb[4*k4+3]*zb[4*k4+3]);
            }
        }
    } else {
        // ---- zero accumulators ----
        int t = (bx - 9)*256 + tid;   // 0..2047
        float4 z4 = make_float4(0.f, 0.f, 0.f, 0.f);
        if (t < 1024) ((float4*)g_psi2)[t] = z4;
        ((float4*)g_A)[t]        = z4;
        ((float4*)g_A)[t + 2048] = z4;
        if (t < 8) g_scal[t] = 0.f;
    }
}

// ================= kBC: psi2 (blocks 0..319) + A-GEMM (blocks 320..447) =====
__global__ void __launch_bounds__(256, 2) kBC(const float* __restrict__ y,
                                              const float* __restrict__ z) {
    int tid = threadIdx.x;
    if (blockIdx.x < 320) {
        // ---- psi2: 2 pairs/thread, 32 n per block ----
        __shared__ alignas(16) float sR[32][36];
        int pg = blockIdx.x / 64;
        int ny = blockIdx.x % 64;
        int p0 = (pg*256 + tid)*2;
        float4 zA[8], zB[8];
        #pragma unroll
        for (int k = 0; k < 8; k++) { zA[k] = g_uz4[p0*8 + k]; zB[k] = g_uz4[(p0+1)*8 + k]; }
        float bA = g_ub[p0], bB = g_ub[p0+1];
        int n0 = ny * 32;
        { int i = tid >> 3, f = tid & 7;
          ((float4*)&sR[i][0])[f] = ((const float4*)&g_row[(n0+i)*32])[f]; }
        if (tid < 32) sR[tid][32] = g_a[n0 + tid];
        __syncthreads();
        float accA = 0.f, accB = 0.f;
        #pragma unroll 4
        for (int i = 0; i < 32; i++) {
            const float4* rv = (const float4*)&sR[i][0];
            float an = sR[i][32];
            float a0 = bA + an, a1 = 0.f, b0 = bB + an, b1 = 0.f;
            #pragma unroll
            for (int k = 0; k < 4; k++) {
                float4 r = rv[k];
                a0 = fmaf(r.x, zA[k].x, a0); a0 = fmaf(r.y, zA[k].y, a0);
                a0 = fmaf(r.z, zA[k].z, a0); a0 = fmaf(r.w, zA[k].w, a0);
                b0 = fmaf(r.x, zB[k].x, b0); b0 = fmaf(r.y, zB[k].y, b0);
                b0 = fmaf(r.z, zB[k].z, b0); b0 = fmaf(r.w, zB[k].w, b0);
            }
            #pragma unroll
            for (int k = 4; k < 8; k++) {
                float4 r = rv[k];
                a1 = fmaf(r.x, zA[k].x, a1); a1 = fmaf(r.y, zA[k].y, a1);
                a1 = fmaf(r.z, zA[k].z, a1); a1 = fmaf(r.w, zA[k].w, a1);
                b1 = fmaf(r.x, zB[k].x, b1); b1 = fmaf(r.y, zB[k].y, b1);
                b1 = fmaf(r.z, zB[k].z, b1); b1 = fmaf(r.w, zB[k].w, b1);
            }
            accA += ex2(a0 + a1);
            accB += ex2(b0 + b1);
        }
        if (p0 < NPAIR) {
            int i = g_upI[p0], j = g_upJ[p0];
            atomicAdd(&g_psi2[i*Mm + j], accA);
            if (i != j) atomicAdd(&g_psi2[j*Mm + i], accA);
        }
        if (p0 + 1 < NPAIR) {
            int i = g_upI[p0+1], j = g_upJ[p0+1];
            atomicAdd(&g_psi2[i*Mm + j], accB);
            if (i != j) atomicAdd(&g_psi2[j*Mm + i], accB);
        }
    } else {
        // ---- fused psi1 + A = psi1^T @ y + sum(y*y) ----
        __shared__ alignas(16) float zs[Mm*Qq];
        __shared__ alignas(16) float sU[16][36];
        __shared__ alignas(16) float sP[16][64];
        __shared__ float red[256];
        int bb = blockIdx.x - 320;
        int d0 = (bb & 7) * 32;
        int n0 = (bb >> 3) * 128;
        ((float4*)zs)[tid] = ((const float4*)z)[tid];   // 1024 floats
        int jg = tid >> 5, dc = tid & 31;
        float acc[8] = {0,0,0,0,0,0,0,0};
        float yy = 0.f;
        for (int s = 0; s < 8; s++) {
            __syncthreads();
            if (tid < 144) {
                int row = tid / 9, f = tid - row*9;
                ((float4*)&sU[row][0])[f] = ((const float4*)&g_pp[(n0 + s*16 + row)*36])[f];
            }
            __syncthreads();
            #pragma unroll
            for (int rr = 0; rr < 4; rr++) {
                int e = tid + 256*rr;
                int nn = e >> 6, j = e & 63;
                float sacc = sU[nn][32];
                #pragma unroll
                for (int q = 0; q < Qq; q++) {
                    float dm = sU[nn][q] - zs[j*Qq + q];
                    sacc = fmaf(-sU[nn][16+q]*dm, dm, sacc);
                }
                sP[nn][j] = ex2(sacc);
            }
            __syncthreads();
            #pragma unroll
            for (int nn = 0; nn < 16; nn++) {
                float yv = y[(n0 + s*16 + nn)*Dd + d0 + dc];
                if (jg == 0) yy = fmaf(yv, yv, yy);
                float4 p0v = ((const float4*)&sP[nn][0])[jg*2];
                float4 p1v = ((const float4*)&sP[nn][0])[jg*2 + 1];
                acc[0] = fmaf(p0v.x, yv, acc[0]); acc[1] = fmaf(p0v.y, yv, acc[1]);
                acc[2] = fmaf(p0v.z, yv, acc[2]); acc[3] = fmaf(p0v.w, yv, acc[3]);
                acc[4] = fmaf(p1v.x, yv, acc[4]); acc[5] = fmaf(p1v.y, yv, acc[5]);
                acc[6] = fmaf(p1v.z, yv, acc[6]); acc[7] = fmaf(p1v.w, yv, acc[7]);
            }
        }
        #pragma unroll
        for (int jj = 0; jj < 8; jj++)
            atomicAdd(&g_A[(jg*8 + jj)*Dd + d0 + dc], acc[jj]);
        __syncthreads();
        red[tid] = yy; __syncthreads();
        #pragma unroll
        for (int s = 128; s > 0; s >>= 1) { if (tid < s) red[tid] += red[tid+s]; __syncthreads(); }
        if (tid == 0) atomicAdd(&g_scal[1], red[0]);
    }
}

// ================= kG: G = A @ A^T (32 blocks, 2 rows each) =================
__global__ void kG() {
    __shared__ alignas(16) float a0s[Dd];
    __shared__ alignas(16) float a1s[Dd];
    __shared__ float sG[Mm][8];
    int tid = threadIdx.x;
    int r0 = blockIdx.x * 2, r1 = r0 + 1;
    a0s[tid] = g_A[r0*Dd + tid];
    a1s[tid] = g_A[r1*Dd + tid];
    __syncthreads();
    int k = tid >> 2, q = tid & 3;
    const float4* bv4  = (const float4*)&g_A[k*Dd + q*64];
    const float4* av04 = (const float4*)&a0s[q*64];
    const float4* av14 = (const float4*)&a1s[q*64];
    float s0 = 0.f, s1 = 0.f;
    #pragma unroll
    for (int d = 0; d < 16; d++) {
        float4 b = bv4[d], a0 = av04[d], a1 = av14[d];
        s0 = fmaf(a0.x,b.x,s0); s0 = fmaf(a0.y,b.y,s0); s0 = fmaf(a0.z,b.z,s0); s0 = fmaf(a0.w,b.w,s0);
        s1 = fmaf(a1.x,b.x,s1); s1 = fmaf(a1.y,b.y,s1); s1 = fmaf(a1.z,b.z,s1); s1 = fmaf(a1.w,b.w,s1);
    }
    sG[k][q] = s0; sG[k][4 + q] = s1;
    __syncthreads();
    if (tid < 64)
        g_G[r0*Mm + tid] = sG[tid][0] + sG[tid][1] + sG[tid][2] + sG[tid][3];
    else if (tid < 128) {
        int t = tid - 64;
        g_G[r1*Mm + t] = sG[t][4] + sG[t][5] + sG[t][6] + sG[t][7];
    }
}

// ===== kD: dual in-place Gauss-Jordan + traces + final scalar (1 block) =====
__global__ void kD(const float* __restrict__ noise, const float* __restrict__ varp,
                   float* __restrict__ out) {
    __shared__ float sM[2][64][68];
    __shared__ float pr[2][64];
    __shared__ float fcol[2][64];
    __shared__ float red[512];
    __shared__ float sres[4];
    int tid = threadIdx.x;
    float beta = 1.0f / softplus_f(noise[0]);
    int mat = tid >> 8;
    int t = tid & 255;
    for (int p = t; p < MMs; p += 256) {
        int i = p >> 6, j = p & 63;
        float v = g_kmm[p];
        if (mat) v = fmaf(beta, g_psi2[p], v);
        sM[mat][i][j] = v;
    }
    __syncthreads();
    int r = t >> 2, c0 = t & 3;
    float ldacc = 0.f;
    for (int k = 0; k < Mm; k++) {
        if (t < 64) {
            float p = sM[mat][k][k];
            float rp = 1.0f / p;
            pr[mat][t]   = (t == k) ? rp : sM[mat][k][t] * rp;
            fcol[mat][t] = sM[mat][t][k];
            if (t == 0) ldacc += logf(p);
        }
        __syncthreads();
        float f = fcol[mat][r];
        float prk = pr[mat][k];
        float4* row4 = (float4*)&sM[mat][r][0];
        const float4* pv4 = (const float4*)&pr[mat][0];
        if (r == k) {
            #pragma unroll
            for (int t4 = 0; t4 < 4; t4++) { int j4 = c0 + 4*t4; row4[j4] = pv4[j4]; }
        } else {
            #pragma unroll
            for (int t4 = 0; t4 < 4; t4++) {
                int j4 = c0 + 4*t4;
                float4 pv = pv4[j4];
                float4 g = row4[j4];
                g.x = fmaf(-f, pv.x, g.x); g.y = fmaf(-f, pv.y, g.y);
                g.z = fmaf(-f, pv.z, g.z); g.w = fmaf(-f, pv.w, g.w);
                row4[j4] = g;
            }
            if (c0 == ((k >> 2) & 3)) sM[mat][r][k] = -f * prk;
        }
        __syncthreads();
    }
    if (t == 0) sres[mat] = ldacc;   // [0]=logdet(kmm), [1]=logdet(cov1)
    __syncthreads();
    // trace(kmm^{-1} psi2)
    float tr = 0.f;
    for (int p = tid; p < MMs; p += 512) tr += sM[0][p >> 6][p & 63] * g_psi2[p];
    red[tid] = tr; __syncthreads();
    #pragma unroll
    for (int s = 256; s > 0; s >>= 1) { if (tid < s) red[tid] += red[tid+s]; __syncthreads(); }
    if (tid == 0) sres[2] = red[0];
    __syncthreads();
    // trace(cov1^{-1} G) = sum(A * cov1^{-1} A)
    float trc = 0.f;
    for (int p = tid; p < MMs; p += 512) trc += sM[1][p >> 6][p & 63] * g_G[p];
    red[tid] = trc; __syncthreads();
    #pragma unroll
    for (int s = 256; s > 0; s >>= 1) { if (tid < s) red[tid] += red[tid+s]; __syncthreads(); }
    if (tid == 0) {
        float var = varp[0];
        double kl = 0.0;
        for (int i = 0; i < 8; i++) kl += (double)g_klpart[i];
        double nd = (double)Nn * (double)Dd;
        kl /= nd;
        double F = 0.5 * Nn * log((double)beta)
                 + 0.5 * (double)sres[0]
                 - 0.5 * Nn * log(3.14159265358979323846)
                 - 0.5 * (double)sres[1]
                 - 0.5 * (double)beta * ((double)Nn * (double)var)
                 + 0.5 * (double)sres[2];
        double tr_yWy = (double)beta * (double)g_scal[1] - (double)red[0];
        F = (F * Dd - 0.5 * tr_yWy) / nd;
        out[0] = (float)(F - kl);
    }
}

extern "C" void kernel_launch(void* const* d_in, const int* in_sizes, int n_in,
                              void* d_out, int out_size) {
    const float* y     = (const float*)d_in[0];
    const float* qmu   = (const float*)d_in[1];
    const float* qls   = (const float*)d_in[2];
    const float* z     = (const float*)d_in[3];
    const float* noise = (const float*)d_in[4];
    const float* alpha = (const float*)d_in[5];
    const float* varp  = (const float*)d_in[6];
    float* out = (float*)d_out;

    kA<<<17, 256>>>(qmu, qls, z, alpha, varp);
    kBC<<<448, 256>>>(y, z);
    kG<<<32, 256>>>();
    kD<<<1, 512>>>(noise, varp, out);
}

// round 3
// speedup vs baseline: 1.4810x; 1.3150x over previous
#include <cuda_runtime.h>
#include <math.h>

#define Nn 2048
#define Dd 256
#define Qq 16
#define Mm 64
#define MMs 4096
#define NPAIR 2080
#define NPAD 2560
#define LOG2E 1.4426950408889634f

// -------- scratch (device globals) --------
__device__ alignas(16) float g_row[Nn*32];
__device__ float  g_a[Nn];
__device__ alignas(16) float g_pp[Nn*36];
__device__ alignas(16) float g_kmm[MMs];
__device__ float  g_ub[NPAD];
__device__ int    g_upI[NPAD];
__device__ int    g_upJ[NPAD];
__device__ alignas(16) float4 g_uz4[NPAD*8];
__device__ alignas(16) float g_psi2[MMs];
__device__ alignas(16) float g_A[Mm*Dd];
__device__ alignas(16) float g_G[MMs];
__device__ float  g_klpart[8];
__device__ float  g_scal[8];

__device__ __forceinline__ float softplus_f(float x) {
    float ax = fabsf(x);
    return fmaxf(x, 0.0f) + log1pf(__expf(-ax));
}
__device__ __forceinline__ float ex2(float x) {
    float y; asm("ex2.approx.f32 %0, %1;" : "=f"(y) : "f"(x)); return y;
}
// FMA-pipe exp2 (avoids MUFU bottleneck). |rel err| ~2.4e-6 on f in [-.5,.5]
__device__ __forceinline__ float exp2_fast(float x) {
    x = fmaxf(x, -125.0f);
    float r = rintf(x);
    float f = x - r;
    int   i = (int)r;
    float p =          1.3333558146e-3f;
    p = fmaf(p, f,     9.6181291076e-3f);
    p = fmaf(p, f,     5.5504108664e-2f);
    p = fmaf(p, f,     2.4022650696e-1f);
    p = fmaf(p, f,     6.9314718056e-1f);
    p = fmaf(p, f,     1.0f);
    return __int_as_float(__float_as_int(p) + (i << 23));
}

// ================= kA: zero + per-n stats + pair tables (17 blocks) =========
__global__ void kA(const float* __restrict__ qmu, const float* __restrict__ qls,
                   const float* __restrict__ z,   const float* __restrict__ alpha,
                   const float* __restrict__ varp) {
    int bx = blockIdx.x, tid = threadIdx.x;
    if (bx < 8) {
        __shared__ float red[256];
        int n = bx * 256 + tid;
        float lv = logf(varp[0]);
        float sum2 = 0.f, s3 = 0.f, P = 0.f, kl = 0.f;
        #pragma unroll
        for (int q = 0; q < Qq; q++) {
            float mu = qmu[n*Qq + q];
            float sg = softplus_f(qls[n*Qq + q]);
            float al = alpha[q];
            kl += -logf(sg) + 0.5f*(sg*sg + mu*mu - 1.0f);
            float d1 = sg*al + 1.0f;
            float d2 = 2.0f*al*sg + 1.0f;
            float w1 = al / d1;
            float w2 = al / d2;
            sum2 += logf(d1);
            s3   += logf(d2);
            P    += w2*mu*mu;
            g_row[n*32 + q]      = LOG2E * 2.0f * w2 * mu;
            g_row[n*32 + 16 + q] = LOG2E * w2;
            g_pp[n*36 + q]       = mu;
            g_pp[n*36 + 16 + q]  = 0.5f * LOG2E * w1;
        }
        g_pp[n*36 + 32] = LOG2E * (2.0f*lv - 0.5f*sum2);
        g_a[n]          = LOG2E * (4.0f*lv - 0.5f*s3 - P);
        red[tid] = kl; __syncthreads();
        #pragma unroll
        for (int s = 128; s > 0; s >>= 1) { if (tid < s) red[tid] += red[tid+s]; __syncthreads(); }
        if (tid == 0) g_klpart[bx] = red[0];
    } else if (bx == 8) {
        __shared__ float zsh[Mm*Qq];
        __shared__ float sal[Qq];
        for (int t = tid; t < Mm*Qq; t += 256) zsh[t] = z[t];
        if (tid < Qq) sal[tid] = alpha[tid];
        __syncthreads();
        float var = varp[0];
        for (int p = tid; p < MMs; p += 256) {
            int i = p >> 6, j = p & 63;
            float S = 0.f;
            #pragma unroll
            for (int q = 0; q < Qq; q++) {
                float dz = zsh[i*Qq + q] - zsh[j*Qq + q];
                S = fmaf(sal[q]*dz, dz, S);
            }
            g_kmm[p] = var * __expf(-0.5f*S);
            if (i <= j) {
                int u = i*Mm - (i*(i-1))/2 + (j - i);
                g_upI[u] = i; g_upJ[u] = j;
                g_ub[u]  = -0.25f * LOG2E * S;
                float zb[Qq];
                #pragma unroll
                for (int q = 0; q < Qq; q++) zb[q] = 0.5f*(zsh[i*Qq+q] + zsh[j*Qq+q]);
                #pragma unroll
                for (int k4 = 0; k4 < 4; k4++)
                    g_uz4[u*8 + k4] = make_float4(zb[4*k4], zb[4*k4+1], zb[4*k4+2], zb[4*k4+3]);
                #pragma unroll
                for (int k4 = 0; k4 < 4; k4++)
                    g_uz4[u*8 + 4 + k4] = make_float4(-zb[4*k4]*zb[4*k4],     -zb[4*k4+1]*zb[4*k4+1],
                                                      -zb[4*k4+2]*zb[4*k4+2], -zb[4*k4+3]*zb[4*k4+3]);
            }
        }
    } else {
        int t = (bx - 9)*256 + tid;
        float4 z4 = make_float4(0.f, 0.f, 0.f, 0.f);
        if (t < 1024) ((float4*)g_psi2)[t] = z4;
        ((float4*)g_A)[t]        = z4;
        ((float4*)g_A)[t + 2048] = z4;
        if (t < 8) g_scal[t] = 0.f;
    }
}

// ================= kBC: psi2 (blocks 0..319) + A-GEMM (blocks 320..447) =====
__global__ void __launch_bounds__(256, 2) kBC(const float* __restrict__ y,
                                              const float* __restrict__ z) {
    int tid = threadIdx.x;
    if (blockIdx.x < 320) {
        __shared__ alignas(16) float sR[32][36];
        int pg = blockIdx.x / 64;
        int ny = blockIdx.x % 64;
        int p0 = (pg*256 + tid)*2;
        float4 zA[8], zB[8];
        #pragma unroll
        for (int k = 0; k < 8; k++) { zA[k] = g_uz4[p0*8 + k]; zB[k] = g_uz4[(p0+1)*8 + k]; }
        float bA = g_ub[p0], bB = g_ub[p0+1];
        int n0 = ny * 32;
        { int i = tid >> 3, f = tid & 7;
          ((float4*)&sR[i][0])[f] = ((const float4*)&g_row[(n0+i)*32])[f]; }
        if (tid < 32) sR[tid][32] = g_a[n0 + tid];
        __syncthreads();
        float accA = 0.f, accB = 0.f;
        #pragma unroll 4
        for (int i = 0; i < 32; i++) {
            const float4* rv = (const float4*)&sR[i][0];
            float an = sR[i][32];
            float a0 = bA + an, a1 = 0.f, b0 = bB + an, b1 = 0.f;
            #pragma unroll
            for (int k = 0; k < 4; k++) {
                float4 r = rv[k];
                a0 = fmaf(r.x, zA[k].x, a0); a0 = fmaf(r.y, zA[k].y, a0);
                a0 = fmaf(r.z, zA[k].z, a0); a0 = fmaf(r.w, zA[k].w, a0);
                b0 = fmaf(r.x, zB[k].x, b0); b0 = fmaf(r.y, zB[k].y, b0);
                b0 = fmaf(r.z, zB[k].z, b0); b0 = fmaf(r.w, zB[k].w, b0);
            }
            #pragma unroll
            for (int k = 4; k < 8; k++) {
                float4 r = rv[k];
                a1 = fmaf(r.x, zA[k].x, a1); a1 = fmaf(r.y, zA[k].y, a1);
                a1 = fmaf(r.z, zA[k].z, a1); a1 = fmaf(r.w, zA[k].w, a1);
                b1 = fmaf(r.x, zB[k].x, b1); b1 = fmaf(r.y, zB[k].y, b1);
                b1 = fmaf(r.z, zB[k].z, b1); b1 = fmaf(r.w, zB[k].w, b1);
            }
            accA += exp2_fast(a0 + a1);
            accB += exp2_fast(b0 + b1);
        }
        if (p0 < NPAIR) {
            int i = g_upI[p0], j = g_upJ[p0];
            atomicAdd(&g_psi2[i*Mm + j], accA);
            if (i != j) atomicAdd(&g_psi2[j*Mm + i], accA);
        }
        if (p0 + 1 < NPAIR) {
            int i = g_upI[p0+1], j = g_upJ[p0+1];
            atomicAdd(&g_psi2[i*Mm + j], accB);
            if (i != j) atomicAdd(&g_psi2[j*Mm + i], accB);
        }
    } else {
        __shared__ alignas(16) float zs[Mm*Qq];
        __shared__ alignas(16) float sU[16][36];
        __shared__ alignas(16) float sP[16][64];
        __shared__ float red[256];
        int bb = blockIdx.x - 320;
        int d0 = (bb & 7) * 32;
        int n0 = (bb >> 3) * 128;
        ((float4*)zs)[tid] = ((const float4*)z)[tid];
        int jg = tid >> 5, dc = tid & 31;
        float acc[8] = {0,0,0,0,0,0,0,0};
        float yy = 0.f;
        for (int s = 0; s < 8; s++) {
            __syncthreads();
            if (tid < 144) {
                int row = tid / 9, f = tid - row*9;
                ((float4*)&sU[row][0])[f] = ((const float4*)&g_pp[(n0 + s*16 + row)*36])[f];
            }
            __syncthreads();
            #pragma unroll
            for (int rr = 0; rr < 4; rr++) {
                int e = tid + 256*rr;
                int nn = e >> 6, j = e & 63;
                float sacc = sU[nn][32];
                #pragma unroll
                for (int q = 0; q < Qq; q++) {
                    float dm = sU[nn][q] - zs[j*Qq + q];
                    sacc = fmaf(-sU[nn][16+q]*dm, dm, sacc);
                }
                sP[nn][j] = ex2(sacc);
            }
            __syncthreads();
            #pragma unroll
            for (int nn = 0; nn < 16; nn++) {
                float yv = y[(n0 + s*16 + nn)*Dd + d0 + dc];
                if (jg == 0) yy = fmaf(yv, yv, yy);
                float4 p0v = ((const float4*)&sP[nn][0])[jg*2];
                float4 p1v = ((const float4*)&sP[nn][0])[jg*2 + 1];
                acc[0] = fmaf(p0v.x, yv, acc[0]); acc[1] = fmaf(p0v.y, yv, acc[1]);
                acc[2] = fmaf(p0v.z, yv, acc[2]); acc[3] = fmaf(p0v.w, yv, acc[3]);
                acc[4] = fmaf(p1v.x, yv, acc[4]); acc[5] = fmaf(p1v.y, yv, acc[5]);
                acc[6] = fmaf(p1v.z, yv, acc[6]); acc[7] = fmaf(p1v.w, yv, acc[7]);
            }
        }
        #pragma unroll
        for (int jj = 0; jj < 8; jj++)
            atomicAdd(&g_A[(jg*8 + jj)*Dd + d0 + dc], acc[jj]);
        __syncthreads();
        red[tid] = yy; __syncthreads();
        #pragma unroll
        for (int s = 128; s > 0; s >>= 1) { if (tid < s) red[tid] += red[tid+s]; __syncthreads(); }
        if (tid == 0) atomicAdd(&g_scal[1], red[0]);
    }
}

// ================= kG: G = A @ A^T (32 blocks, 2 rows each) =================
__global__ void kG() {
    __shared__ alignas(16) float a0s[Dd];
    __shared__ alignas(16) float a1s[Dd];
    __shared__ float sG[Mm][8];
    int tid = threadIdx.x;
    int r0 = blockIdx.x * 2, r1 = r0 + 1;
    a0s[tid] = g_A[r0*Dd + tid];
    a1s[tid] = g_A[r1*Dd + tid];
    __syncthreads();
    int k = tid >> 2, q = tid & 3;
    const float4* bv4  = (const float4*)&g_A[k*Dd + q*64];
    const float4* av04 = (const float4*)&a0s[q*64];
    const float4* av14 = (const float4*)&a1s[q*64];
    float s0 = 0.f, s1 = 0.f;
    #pragma unroll
    for (int d = 0; d < 16; d++) {
        float4 b = bv4[d], a0 = av04[d], a1 = av14[d];
        s0 = fmaf(a0.x,b.x,s0); s0 = fmaf(a0.y,b.y,s0); s0 = fmaf(a0.z,b.z,s0); s0 = fmaf(a0.w,b.w,s0);
        s1 = fmaf(a1.x,b.x,s1); s1 = fmaf(a1.y,b.y,s1); s1 = fmaf(a1.z,b.z,s1); s1 = fmaf(a1.w,b.w,s1);
    }
    sG[k][q] = s0; sG[k][4 + q] = s1;
    __syncthreads();
    if (tid < 64)
        g_G[r0*Mm + tid] = sG[tid][0] + sG[tid][1] + sG[tid][2] + sG[tid][3];
    else if (tid < 128) {
        int t = tid - 64;
        g_G[r1*Mm + t] = sG[t][4] + sG[t][5] + sG[t][6] + sG[t][7];
    }
}

// ===== kD: two warp-register Gauss-Jordan inversions, zero barriers =========
// warp 0: kmm, warp 1: cov1 = kmm + beta*psi2. Lane owns rows lane, lane+32
// entirely in registers; pivot row broadcast via shfl; fully unrolled.
#define GJS(kk, H) {                                                          \
    const int src = (kk) & 31;                                                \
    float p = __shfl_sync(0xffffffffu, (H) ? row1[(kk)] : row0[(kk)], src);   \
    float rp; asm("rcp.approx.f32 %0, %1;" : "=f"(rp) : "f"(p));              \
    rp = rp * (2.0f - p * rp);                                                \
    float lg; asm("lg2.approx.f32 %0, %1;" : "=f"(lg) : "f"(p));              \
    ld += lg;                                                                 \
    float f0 = row0[(kk)], f1 = row1[(kk)];                                   \
    bool own0 = (!(H)) && (lane == src);                                      \
    bool own1 = (H) && (lane == src);                                         \
    float fr0 = own0 ? (1.0f - rp) : f0 * rp;                                 \
    float fr1 = own1 ? (1.0f - rp) : f1 * rp;                                 \
    _Pragma("unroll")                                                         \
    for (int j = 0; j < 64; j++) {                                            \
        float pj = __shfl_sync(0xffffffffu, (H) ? row1[j] : row0[j], src);    \
        row0[j] = fmaf(-fr0, pj, row0[j]);                                    \
        row1[j] = fmaf(-fr1, pj, row1[j]);                                    \
    }                                                                         \
    row0[(kk)] = own0 ? rp : -f0 * rp;                                        \
    row1[(kk)] = own1 ? rp : -f1 * rp;                                        \
}

__global__ void __launch_bounds__(64, 1) kD(const float* __restrict__ noise,
                                            const float* __restrict__ varp,
                                            float* __restrict__ out) {
    __shared__ float sres[4];
    int lane = threadIdx.x & 31;
    int w = threadIdx.x >> 5;        // 0: kmm, 1: cov1
    float beta = 1.0f / softplus_f(noise[0]);

    float row0[64], row1[64];
    #pragma unroll
    for (int j4 = 0; j4 < 16; j4++) {
        float4 a = ((const float4*)&g_kmm[lane*64])[j4];
        float4 b = ((const float4*)&g_kmm[(lane+32)*64])[j4];
        if (w) {
            float4 pa = ((const float4*)&g_psi2[lane*64])[j4];
            float4 pb = ((const float4*)&g_psi2[(lane+32)*64])[j4];
            a.x = fmaf(beta, pa.x, a.x); a.y = fmaf(beta, pa.y, a.y);
            a.z = fmaf(beta, pa.z, a.z); a.w = fmaf(beta, pa.w, a.w);
            b.x = fmaf(beta, pb.x, b.x); b.y = fmaf(beta, pb.y, b.y);
            b.z = fmaf(beta, pb.z, b.z); b.w = fmaf(beta, pb.w, b.w);
        }
        row0[4*j4+0] = a.x; row0[4*j4+1] = a.y; row0[4*j4+2] = a.z; row0[4*j4+3] = a.w;
        row1[4*j4+0] = b.x; row1[4*j4+1] = b.y; row1[4*j4+2] = b.z; row1[4*j4+3] = b.w;
    }
    float ld = 0.f;
    #pragma unroll
    for (int k = 0; k < 32; k++) GJS(k, 0);
    #pragma unroll
    for (int k = 32; k < 64; k++) GJS(k, 1);

    // trace: warp0 sum(inv_kmm * psi2), warp1 sum(inv_cov1 * G); both symmetric
    const float4* T4 = (const float4*)(w ? g_G : g_psi2);
    float tr = 0.f;
    #pragma unroll
    for (int j4 = 0; j4 < 16; j4++) {
        float4 t0 = T4[lane*16 + j4];
        float4 t1 = T4[(lane+32)*16 + j4];
        tr = fmaf(row0[4*j4+0], t0.x, tr); tr = fmaf(row0[4*j4+1], t0.y, tr);
        tr = fmaf(row0[4*j4+2], t0.z, tr); tr = fmaf(row0[4*j4+3], t0.w, tr);
        tr = fmaf(row1[4*j4+0], t1.x, tr); tr = fmaf(row1[4*j4+1], t1.y, tr);
        tr = fmaf(row1[4*j4+2], t1.z, tr); tr = fmaf(row1[4*j4+3], t1.w, tr);
    }
    #pragma unroll
    for (int s = 16; s > 0; s >>= 1) tr += __shfl_xor_sync(0xffffffffu, tr, s);
    if (lane == 0) { sres[w] = ld * 0.6931471805599453f; sres[2 + w] = tr; }
    __syncthreads();
    if (threadIdx.x == 0) {
        float var = varp[0];
        double kl = 0.0;
        for (int i = 0; i < 8; i++) kl += (double)g_klpart[i];
        double nd = (double)Nn * (double)Dd;
        kl /= nd;
        double F = 0.5 * Nn * log((double)beta)
                 + 0.5 * (double)sres[0]
                 - 0.5 * Nn * log(3.14159265358979323846)
                 - 0.5 * (double)sres[1]
                 - 0.5 * (double)beta * ((double)Nn * (double)var)
                 + 0.5 * (double)sres[2];
        double tr_yWy = (double)beta * (double)g_scal[1] - (double)sres[3];
        F = (F * Dd - 0.5 * tr_yWy) / nd;
        out[0] = (float)(F - kl);
    }
}

extern "C" void kernel_launch(void* const* d_in, const int* in_sizes, int n_in,
                              void* d_out, int out_size) {
    const float* y     = (const float*)d_in[0];
    const float* qmu   = (const float*)d_in[1];
    const float* qls   = (const float*)d_in[2];
    const float* z     = (const float*)d_in[3];
    const float* noise = (const float*)d_in[4];
    const float* alpha = (const float*)d_in[5];
    const float* varp  = (const float*)d_in[6];
    float* out = (float*)d_out;

    kA<<<17, 256>>>(qmu, qls, z, alpha, varp);
    kBC<<<448, 256>>>(y, z);
    kG<<<32, 256>>>();
    kD<<<1, 64>>>(noise, varp, out);
}

// round 4
// speedup vs baseline: 1.8911x; 1.2769x over previous
#include <cuda_runtime.h>
#include <math.h>

#define Nn 2048
#define Dd 256
#define Qq 16
#define Mm 64
#define MMs 4096
#define NPAIR 2080
#define NPAD 2560
#define LOG2E 1.4426950408889634f

// -------- scratch (device globals) --------
__device__ alignas(16) float g_row[Nn*32];
__device__ float  g_a[Nn];
__device__ alignas(16) float g_pp[Nn*36];
__device__ alignas(16) float g_kmm[MMs];
__device__ float  g_ub[NPAD];
__device__ int    g_upI[NPAD];
__device__ int    g_upJ[NPAD];
__device__ alignas(16) float4 g_uz4[NPAD*8];
__device__ alignas(16) float g_psi2[MMs];
__device__ alignas(16) float g_A[Mm*Dd];
__device__ alignas(16) float g_G[MMs];
__device__ float  g_klpart[8];
__device__ float  g_scal[8];

__device__ __forceinline__ float softplus_f(float x) {
    float ax = fabsf(x);
    return fmaxf(x, 0.0f) + log1pf(__expf(-ax));
}
__device__ __forceinline__ float ex2(float x) {
    float y; asm("ex2.approx.f32 %0, %1;" : "=f"(y) : "f"(x)); return y;
}
// FMA-pipe exp2 (avoids MUFU bottleneck). |rel err| ~2.4e-6
__device__ __forceinline__ float exp2_fast(float x) {
    x = fmaxf(x, -125.0f);
    float r = rintf(x);
    float f = x - r;
    int   i = (int)r;
    float p =          1.3333558146e-3f;
    p = fmaf(p, f,     9.6181291076e-3f);
    p = fmaf(p, f,     5.5504108664e-2f);
    p = fmaf(p, f,     2.4022650696e-1f);
    p = fmaf(p, f,     6.9314718056e-1f);
    p = fmaf(p, f,     1.0f);
    return __int_as_float(__float_as_int(p) + (i << 23));
}

// ================= kA: zero + per-n stats + pair tables (17 blocks) =========
__global__ void kA(const float* __restrict__ qmu, const float* __restrict__ qls,
                   const float* __restrict__ z,   const float* __restrict__ alpha,
                   const float* __restrict__ varp) {
    int bx = blockIdx.x, tid = threadIdx.x;
    if (bx < 8) {
        __shared__ float red[256];
        int n = bx * 256 + tid;
        float lv = logf(varp[0]);
        float sum2 = 0.f, s3 = 0.f, P = 0.f, kl = 0.f;
        #pragma unroll
        for (int q = 0; q < Qq; q++) {
            float mu = qmu[n*Qq + q];
            float sg = softplus_f(qls[n*Qq + q]);
            float al = alpha[q];
            kl += -logf(sg) + 0.5f*(sg*sg + mu*mu - 1.0f);
            float d1 = sg*al + 1.0f;
            float d2 = 2.0f*al*sg + 1.0f;
            float w1 = al / d1;
            float w2 = al / d2;
            sum2 += logf(d1);
            s3   += logf(d2);
            P    += w2*mu*mu;
            g_row[n*32 + q]      = LOG2E * 2.0f * w2 * mu;
            g_row[n*32 + 16 + q] = LOG2E * w2;
            g_pp[n*36 + q]       = mu;
            g_pp[n*36 + 16 + q]  = 0.5f * LOG2E * w1;
        }
        g_pp[n*36 + 32] = LOG2E * (2.0f*lv - 0.5f*sum2);
        g_a[n]          = LOG2E * (4.0f*lv - 0.5f*s3 - P);
        red[tid] = kl; __syncthreads();
        #pragma unroll
        for (int s = 128; s > 0; s >>= 1) { if (tid < s) red[tid] += red[tid+s]; __syncthreads(); }
        if (tid == 0) g_klpart[bx] = red[0];
    } else if (bx == 8) {
        __shared__ float zsh[Mm*Qq];
        __shared__ float sal[Qq];
        for (int t = tid; t < Mm*Qq; t += 256) zsh[t] = z[t];
        if (tid < Qq) sal[tid] = alpha[tid];
        __syncthreads();
        float var = varp[0];
        for (int p = tid; p < MMs; p += 256) {
            int i = p >> 6, j = p & 63;
            float S = 0.f;
            #pragma unroll
            for (int q = 0; q < Qq; q++) {
                float dz = zsh[i*Qq + q] - zsh[j*Qq + q];
                S = fmaf(sal[q]*dz, dz, S);
            }
            g_kmm[p] = var * __expf(-0.5f*S);
            if (i <= j) {
                int u = i*Mm - (i*(i-1))/2 + (j - i);
                g_upI[u] = i; g_upJ[u] = j;
                g_ub[u]  = -0.25f * LOG2E * S;
                float zb[Qq];
                #pragma unroll
                for (int q = 0; q < Qq; q++) zb[q] = 0.5f*(zsh[i*Qq+q] + zsh[j*Qq+q]);
                #pragma unroll
                for (int k4 = 0; k4 < 4; k4++)
                    g_uz4[u*8 + k4] = make_float4(zb[4*k4], zb[4*k4+1], zb[4*k4+2], zb[4*k4+3]);
                #pragma unroll
                for (int k4 = 0; k4 < 4; k4++)
                    g_uz4[u*8 + 4 + k4] = make_float4(-zb[4*k4]*zb[4*k4],     -zb[4*k4+1]*zb[4*k4+1],
                                                      -zb[4*k4+2]*zb[4*k4+2], -zb[4*k4+3]*zb[4*k4+3]);
            }
        }
    } else {
        int t = (bx - 9)*256 + tid;
        float4 z4 = make_float4(0.f, 0.f, 0.f, 0.f);
        if (t < 1024) ((float4*)g_psi2)[t] = z4;
        ((float4*)g_A)[t]        = z4;
        ((float4*)g_A)[t + 2048] = z4;
        if (t < 8) g_scal[t] = 0.f;
    }
}

// ================= kBC: psi2 (blocks 0..319) + A-GEMM (blocks 320..447) =====
__global__ void __launch_bounds__(256, 2) kBC(const float* __restrict__ y,
                                              const float* __restrict__ z) {
    int tid = threadIdx.x;
    if (blockIdx.x < 320) {
        __shared__ alignas(16) float sR[32][36];
        int pg = blockIdx.x / 64;
        int ny = blockIdx.x % 64;
        int p0 = (pg*256 + tid)*2;
        float4 zA[8], zB[8];
        #pragma unroll
        for (int k = 0; k < 8; k++) { zA[k] = g_uz4[p0*8 + k]; zB[k] = g_uz4[(p0+1)*8 + k]; }
        float bA = g_ub[p0], bB = g_ub[p0+1];
        int n0 = ny * 32;
        { int i = tid >> 3, f = tid & 7;
          ((float4*)&sR[i][0])[f] = ((const float4*)&g_row[(n0+i)*32])[f]; }
        if (tid < 32) sR[tid][32] = g_a[n0 + tid];
        __syncthreads();
        float accA = 0.f, accB = 0.f;
        #pragma unroll 4
        for (int i = 0; i < 32; i++) {
            const float4* rv = (const float4*)&sR[i][0];
            float an = sR[i][32];
            float a0 = bA + an, a1 = 0.f, b0 = bB + an, b1 = 0.f;
            #pragma unroll
            for (int k = 0; k < 4; k++) {
                float4 r = rv[k];
                a0 = fmaf(r.x, zA[k].x, a0); a0 = fmaf(r.y, zA[k].y, a0);
                a0 = fmaf(r.z, zA[k].z, a0); a0 = fmaf(r.w, zA[k].w, a0);
                b0 = fmaf(r.x, zB[k].x, b0); b0 = fmaf(r.y, zB[k].y, b0);
                b0 = fmaf(r.z, zB[k].z, b0); b0 = fmaf(r.w, zB[k].w, b0);
            }
            #pragma unroll
            for (int k = 4; k < 8; k++) {
                float4 r = rv[k];
                a1 = fmaf(r.x, zA[k].x, a1); a1 = fmaf(r.y, zA[k].y, a1);
                a1 = fmaf(r.z, zA[k].z, a1); a1 = fmaf(r.w, zA[k].w, a1);
                b1 = fmaf(r.x, zB[k].x, b1); b1 = fmaf(r.y, zB[k].y, b1);
                b1 = fmaf(r.z, zB[k].z, b1); b1 = fmaf(r.w, zB[k].w, b1);
            }
            accA += exp2_fast(a0 + a1);
            accB += exp2_fast(b0 + b1);
        }
        if (p0 < NPAIR) {
            int i = g_upI[p0], j = g_upJ[p0];
            atomicAdd(&g_psi2[i*Mm + j], accA);
            if (i != j) atomicAdd(&g_psi2[j*Mm + i], accA);
        }
        if (p0 + 1 < NPAIR) {
            int i = g_upI[p0+1], j = g_upJ[p0+1];
            atomicAdd(&g_psi2[i*Mm + j], accB);
            if (i != j) atomicAdd(&g_psi2[j*Mm + i], accB);
        }
    } else {
        __shared__ alignas(16) float zs[Mm*Qq];
        __shared__ alignas(16) float sU[16][36];
        __shared__ alignas(16) float sP[16][64];
        __shared__ float red[256];
        int bb = blockIdx.x - 320;
        int d0 = (bb & 7) * 32;
        int n0 = (bb >> 3) * 128;
        ((float4*)zs)[tid] = ((const float4*)z)[tid];
        int jg = tid >> 5, dc = tid & 31;
        float acc[8] = {0,0,0,0,0,0,0,0};
        float yy = 0.f;
        for (int s = 0; s < 8; s++) {
            __syncthreads();
            if (tid < 144) {
                int row = tid / 9, f = tid - row*9;
                ((float4*)&sU[row][0])[f] = ((const float4*)&g_pp[(n0 + s*16 + row)*36])[f];
            }
            __syncthreads();
            #pragma unroll
            for (int rr = 0; rr < 4; rr++) {
                int e = tid + 256*rr;
                int nn = e >> 6, j = e & 63;
                float sacc = sU[nn][32];
                #pragma unroll
                for (int q = 0; q < Qq; q++) {
                    float dm = sU[nn][q] - zs[j*Qq + q];
                    sacc = fmaf(-sU[nn][16+q]*dm, dm, sacc);
                }
                sP[nn][j] = ex2(sacc);
            }
            __syncthreads();
            #pragma unroll
            for (int nn = 0; nn < 16; nn++) {
                float yv = y[(n0 + s*16 + nn)*Dd + d0 + dc];
                if (jg == 0) yy = fmaf(yv, yv, yy);
                float4 p0v = ((const float4*)&sP[nn][0])[jg*2];
                float4 p1v = ((const float4*)&sP[nn][0])[jg*2 + 1];
                acc[0] = fmaf(p0v.x, yv, acc[0]); acc[1] = fmaf(p0v.y, yv, acc[1]);
                acc[2] = fmaf(p0v.z, yv, acc[2]); acc[3] = fmaf(p0v.w, yv, acc[3]);
                acc[4] = fmaf(p1v.x, yv, acc[4]); acc[5] = fmaf(p1v.y, yv, acc[5]);
                acc[6] = fmaf(p1v.z, yv, acc[6]); acc[7] = fmaf(p1v.w, yv, acc[7]);
            }
        }
        #pragma unroll
        for (int jj = 0; jj < 8; jj++)
            atomicAdd(&g_A[(jg*8 + jj)*Dd + d0 + dc], acc[jj]);
        __syncthreads();
        red[tid] = yy; __syncthreads();
        #pragma unroll
        for (int s = 128; s > 0; s >>= 1) { if (tid < s) red[tid] += red[tid+s]; __syncthreads(); }
        if (tid == 0) atomicAdd(&g_scal[1], red[0]);
    }
}

// ================= kG: G = A @ A^T (32 blocks, 2 rows each) =================
__global__ void kG() {
    __shared__ alignas(16) float a0s[Dd];
    __shared__ alignas(16) float a1s[Dd];
    __shared__ float sG[Mm][8];
    int tid = threadIdx.x;
    int r0 = blockIdx.x * 2, r1 = r0 + 1;
    a0s[tid] = g_A[r0*Dd + tid];
    a1s[tid] = g_A[r1*Dd + tid];
    __syncthreads();
    int k = tid >> 2, q = tid & 3;
    const float4* bv4  = (const float4*)&g_A[k*Dd + q*64];
    const float4* av04 = (const float4*)&a0s[q*64];
    const float4* av14 = (const float4*)&a1s[q*64];
    float s0 = 0.f, s1 = 0.f;
    #pragma unroll
    for (int d = 0; d < 16; d++) {
        float4 b = bv4[d], a0 = av04[d], a1 = av14[d];
        s0 = fmaf(a0.x,b.x,s0); s0 = fmaf(a0.y,b.y,s0); s0 = fmaf(a0.z,b.z,s0); s0 = fmaf(a0.w,b.w,s0);
        s1 = fmaf(a1.x,b.x,s1); s1 = fmaf(a1.y,b.y,s1); s1 = fmaf(a1.z,b.z,s1); s1 = fmaf(a1.w,b.w,s1);
    }
    sG[k][q] = s0; sG[k][4 + q] = s1;
    __syncthreads();
    if (tid < 64)
        g_G[r0*Mm + tid] = sG[tid][0] + sG[tid][1] + sG[tid][2] + sG[tid][3];
    else if (tid < 128) {
        int t = tid - 64;
        g_G[r1*Mm + t] = sG[t][4] + sG[t][5] + sG[t][6] + sG[t][7];
    }
}

// ===== kD: dual Gauss-Jordan, 32 regs/thread (half-row), smem pivot bcast ===
// 256 threads: mat = tid>>7; t = tid&127; row r = t>>1; half h = t&1.
// Each thread owns M[r][h*32 .. h*32+31] in registers (static indices via full
// unroll). Pivot row double-buffered in smem; f = M[r][k] via pair-shfl.
__global__ void __launch_bounds__(256, 1) kD(const float* __restrict__ noise,
                                             const float* __restrict__ varp,
                                             float* __restrict__ out) {
    __shared__ alignas(16) float spiv[2][2][Mm];
    __shared__ float swarp[8];
    __shared__ float sres[4];
    int tid  = threadIdx.x;
    int mat  = tid >> 7;
    int t    = tid & 127;
    int r    = t >> 1;
    int h    = t & 1;
    int lane = tid & 31;
    float beta = 1.0f / softplus_f(noise[0]);

    float c[32];
    {
        const float4* K4 = (const float4*)&g_kmm[r*64 + h*32];
        const float4* P4 = (const float4*)&g_psi2[r*64 + h*32];
        #pragma unroll
        for (int j4 = 0; j4 < 8; j4++) {
            float4 a = K4[j4];
            if (mat) {
                float4 p = P4[j4];
                a.x = fmaf(beta, p.x, a.x); a.y = fmaf(beta, p.y, a.y);
                a.z = fmaf(beta, p.z, a.z); a.w = fmaf(beta, p.w, a.w);
            }
            c[4*j4+0] = a.x; c[4*j4+1] = a.y; c[4*j4+2] = a.z; c[4*j4+3] = a.w;
        }
    }

    float ld = 0.f;
    #pragma unroll
    for (int k = 0; k < 64; k++) {
        const int buf = k & 1, khalf = k >> 5, kk = k & 31;
        if (r == k) {
            float4* s4 = (float4*)&spiv[mat][buf][h*32];
            #pragma unroll
            for (int j4 = 0; j4 < 8; j4++)
                s4[j4] = make_float4(c[4*j4], c[4*j4+1], c[4*j4+2], c[4*j4+3]);
        }
        __syncthreads();
        float p = spiv[mat][buf][k];
        float rp; asm("rcp.approx.f32 %0, %1;" : "=f"(rp) : "f"(p));
        rp = rp * (2.0f - p * rp);
        float lg; asm("lg2.approx.f32 %0, %1;" : "=f"(lg) : "f"(p));
        ld += lg;
        float f = __shfl_sync(0xffffffffu, c[kk], (lane & ~1) | khalf);
        bool own = (r == k);
        float fr = own ? (1.0f - rp) : f * rp;
        const float4* pv4 = (const float4*)&spiv[mat][buf][h*32];
        #pragma unroll
        for (int j4 = 0; j4 < 8; j4++) {
            float4 pv = pv4[j4];
            c[4*j4+0] = fmaf(-fr, pv.x, c[4*j4+0]);
            c[4*j4+1] = fmaf(-fr, pv.y, c[4*j4+1]);
            c[4*j4+2] = fmaf(-fr, pv.z, c[4*j4+2]);
            c[4*j4+3] = fmaf(-fr, pv.w, c[4*j4+3]);
        }
        if (khalf == h) c[kk] = own ? rp : -f * rp;
    }

    // traces: mat0 sum(invK * psi2), mat1 sum(invC * G)
    const float4* T4 = (const float4*)((mat ? g_G : g_psi2) + r*64 + h*32);
    float tr = 0.f;
    #pragma unroll
    for (int j4 = 0; j4 < 8; j4++) {
        float4 tv = T4[j4];
        tr = fmaf(c[4*j4+0], tv.x, tr); tr = fmaf(c[4*j4+1], tv.y, tr);
        tr = fmaf(c[4*j4+2], tv.z, tr); tr = fmaf(c[4*j4+3], tv.w, tr);
    }
    #pragma unroll
    for (int s = 16; s > 0; s >>= 1) tr += __shfl_xor_sync(0xffffffffu, tr, s);
    if (lane == 0) swarp[tid >> 5] = tr;
    if (t == 0)    sres[mat] = ld * 0.6931471805599453f;
    __syncthreads();
    if (tid == 0) {
        float tr0 = swarp[0] + swarp[1] + swarp[2] + swarp[3];
        float tr1 = swarp[4] + swarp[5] + swarp[6] + swarp[7];
        float var = varp[0];
        double kl = 0.0;
        for (int i = 0; i < 8; i++) kl += (double)g_klpart[i];
        double nd = (double)Nn * (double)Dd;
        kl /= nd;
        double F = 0.5 * Nn * log((double)beta)
                 + 0.5 * (double)sres[0]
                 - 0.5 * Nn * log(3.14159265358979323846)
                 - 0.5 * (double)sres[1]
                 - 0.5 * (double)beta * ((double)Nn * (double)var)
                 + 0.5 * (double)tr0;
        double tr_yWy = (double)beta * (double)g_scal[1] - (double)tr1;
        F = (F * Dd - 0.5 * tr_yWy) / nd;
        out[0] = (float)(F - kl);
    }
}

extern "C" void kernel_launch(void* const* d_in, const int* in_sizes, int n_in,
                              void* d_out, int out_size) {
    const float* y     = (const float*)d_in[0];
    const float* qmu   = (const float*)d_in[1];
    const float* qls   = (const float*)d_in[2];
    const float* z     = (const float*)d_in[3];
    const float* noise = (const float*)d_in[4];
    const float* alpha = (const float*)d_in[5];
    const float* varp  = (const float*)d_in[6];
    float* out = (float*)d_out;

    kA<<<17, 256>>>(qmu, qls, z, alpha, varp);
    kBC<<<448, 256>>>(y, z);
    kG<<<32, 256>>>();
    kD<<<1, 256>>>(noise, varp, out);
}